// round 2
// baseline (speedup 1.0000x reference)
#include <cuda_runtime.h>
#include <math.h>

#define B_SZ 32
#define T_SZ 256
#define DB   768
#define H_SZ 256
#define DL   512    // 2*H
#define XA   10

// ---------------- scratch (device globals; no allocation allowed) ----------
__device__ float g_xz[B_SZ * T_SZ * 2048];   // [b][t][fwd 1024 | bwd 1024]
__device__ float g_h[B_SZ * T_SZ * DL];      // [b][t][hf 256 | hb 256]
__device__ float g_state[2][2][B_SZ * H_SZ]; // ping-pong [p][dir][b*256+j]
__device__ float g_s[B_SZ * T_SZ * 20];      // [row][sq 10 | sk 10]
__device__ float g_w[B_SZ * T_SZ * T_SZ];    // softmax weights
__device__ float g_ctx[B_SZ * T_SZ * DL];    // context
__device__ unsigned int g_barc;
__device__ unsigned int g_barg;

// ---------------- generation grid barrier (blocks co-resident) -------------
__device__ __forceinline__ void grid_barrier(unsigned int nblocks) {
    __syncthreads();
    if (threadIdx.x == 0) {
        __threadfence();
        unsigned int gen = atomicAdd(&g_barg, 0u);
        unsigned int a = atomicAdd(&g_barc, 1u);
        if (a == nblocks - 1u) {
            g_barc = 0u;
            __threadfence();
            atomicAdd(&g_barg, 1u);
        } else {
            while (atomicAdd(&g_barg, 0u) == gen) { __nanosleep(64); }
        }
        __threadfence();
    }
    __syncthreads();
}

__device__ __forceinline__ float sigmoidf_(float x) {
    return 1.0f / (1.0f + expf(-x));
}

// ============================================================
// 1) xz = x @ [Wih_f | Wih_b]^T + bias    M=8192, N=2048, K=768
// ============================================================
__global__ __launch_bounds__(256) void gemm_xz_kernel(
    const float* __restrict__ x,
    const float* __restrict__ Wf, const float* __restrict__ Wb,
    const float* __restrict__ bf, const float* __restrict__ bb)
{
    __shared__ __align__(16) float As[16][68];
    __shared__ __align__(16) float Bs[16][68];
    int n0 = blockIdx.x * 64;
    int m0 = blockIdx.y * 64;
    const float* W;
    const float* bias;
    if (n0 < 1024) { W = Wf + n0 * DB;          bias = bf + n0; }
    else           { W = Wb + (n0 - 1024) * DB; bias = bb + (n0 - 1024); }
    const float* A = x + m0 * DB;
    int tid = threadIdx.x;
    int lr = tid >> 2;            // 0..63
    int lk = (tid & 3) << 2;      // 0,4,8,12
    int tx = tid & 15, ty = tid >> 4;
    float acc[4][4] = {};
    for (int k0 = 0; k0 < DB; k0 += 16) {
        float4 av = *reinterpret_cast<const float4*>(A + lr * DB + k0 + lk);
        float4 bv = *reinterpret_cast<const float4*>(W + lr * DB + k0 + lk);
        As[lk + 0][lr] = av.x; As[lk + 1][lr] = av.y; As[lk + 2][lr] = av.z; As[lk + 3][lr] = av.w;
        Bs[lk + 0][lr] = bv.x; Bs[lk + 1][lr] = bv.y; Bs[lk + 2][lr] = bv.z; Bs[lk + 3][lr] = bv.w;
        __syncthreads();
        #pragma unroll
        for (int k = 0; k < 16; k++) {
            float4 a4 = *reinterpret_cast<const float4*>(&As[k][ty << 2]);
            float4 b4 = *reinterpret_cast<const float4*>(&Bs[k][tx << 2]);
            float am[4] = {a4.x, a4.y, a4.z, a4.w};
            float bn[4] = {b4.x, b4.y, b4.z, b4.w};
            #pragma unroll
            for (int i = 0; i < 4; i++)
                #pragma unroll
                for (int j = 0; j < 4; j++)
                    acc[i][j] = fmaf(am[i], bn[j], acc[i][j]);
        }
        __syncthreads();
    }
    #pragma unroll
    for (int i = 0; i < 4; i++) {
        int m = m0 + (ty << 2) + i;
        #pragma unroll
        for (int j = 0; j < 4; j++) {
            int nl = (tx << 2) + j;
            g_xz[m * 2048 + n0 + nl] = acc[i][j] + bias[nl];
        }
    }
}

// ============================================================
// 2) Bi-LSTM recurrence: persistent, 32 blocks x 128 threads.
//    block = (dir, 16-unit hidden chunk). Whh slice in smem for the
//    whole kernel; c in registers; h ping-pongs through L2.
// ============================================================
__global__ __launch_bounds__(128) void lstm_kernel(
    const float* __restrict__ Whh_f, const float* __restrict__ Whh_b)
{
    extern __shared__ float sm[];
    float* whh_s = sm;            // 64 rows x 260 (padded)
    float* h_s = sm + 64 * 260;   // 32 rows x 260 (padded)

    int tid = threadIdx.x;
    int dir = blockIdx.x >> 4;
    int jc = blockIdx.x & 15;
    int j0 = jc * 16;
    const float* Whh = dir ? Whh_b : Whh_f;

    // stage Whh slice: row lg = gi*16+jl holds Whh[gi*H + j0 + jl][:]
    for (int i = tid; i < 64 * 256; i += 128) {
        int lg = i >> 8, k = i & 255;
        int row = (lg >> 4) * H_SZ + j0 + (lg & 15);
        whh_s[lg * 260 + k] = Whh[row * H_SZ + k];
    }
    // zero my slice of state buffer 0
    for (int i = tid; i < 32 * 16; i += 128) {
        int b = i >> 4, jl = i & 15;
        g_state[0][dir][b * H_SZ + j0 + jl] = 0.0f;
    }
    __threadfence();
    grid_barrier(32);

    int bq = tid & 7;      // batch b = bq + 8*bi
    int gq = tid >> 3;     // hidden unit jl = gq (0..15)
    float c_reg[4] = {0.f, 0.f, 0.f, 0.f};
    int p = 0;

    const float4* w4 = reinterpret_cast<const float4*>(whh_s);
    const float4* h4 = reinterpret_cast<const float4*>(h_s);
    float4* h4w = reinterpret_cast<float4*>(h_s);

    for (int t = 0; t < T_SZ; t++) {
        // load full previous h for this dir (L2, bypass L1)
        const float4* src = reinterpret_cast<const float4*>(&g_state[p][dir][0]);
        for (int i4 = tid; i4 < 2048; i4 += 128) {
            float4 v = __ldcg(src + i4);
            int b = i4 >> 6, k4 = i4 & 63;
            h4w[b * 65 + k4] = v;
        }
        __syncthreads();

        int trow = dir ? (255 - t) : t;
        float acc[4][4];
        #pragma unroll
        for (int bi = 0; bi < 4; bi++) {
            int b = bq + 8 * bi;
            int base = (b * T_SZ + trow) * 2048 + dir * 1024 + j0 + gq;
            #pragma unroll
            for (int gi = 0; gi < 4; gi++)
                acc[bi][gi] = g_xz[base + gi * H_SZ];
        }
        #pragma unroll 2
        for (int k4 = 0; k4 < 64; k4++) {
            float4 hv[4], wv[4];
            #pragma unroll
            for (int bi = 0; bi < 4; bi++) hv[bi] = h4[(bq + 8 * bi) * 65 + k4];
            #pragma unroll
            for (int gi = 0; gi < 4; gi++) wv[gi] = w4[(gq + 16 * gi) * 65 + k4];
            #pragma unroll
            for (int bi = 0; bi < 4; bi++)
                #pragma unroll
                for (int gi = 0; gi < 4; gi++) {
                    acc[bi][gi] = fmaf(hv[bi].x, wv[gi].x, acc[bi][gi]);
                    acc[bi][gi] = fmaf(hv[bi].y, wv[gi].y, acc[bi][gi]);
                    acc[bi][gi] = fmaf(hv[bi].z, wv[gi].z, acc[bi][gi]);
                    acc[bi][gi] = fmaf(hv[bi].w, wv[gi].w, acc[bi][gi]);
                }
        }
        // gates + state update (thread owns its (b, j) cell for all 4 gates)
        #pragma unroll
        for (int bi = 0; bi < 4; bi++) {
            int b = bq + 8 * bi;
            float ig = sigmoidf_(acc[bi][0]);
            float fg = sigmoidf_(acc[bi][1]);
            float gg = tanhf(acc[bi][2]);
            float og = sigmoidf_(acc[bi][3]);
            float c = fmaf(fg, c_reg[bi], ig * gg);
            c_reg[bi] = c;
            float h = og * tanhf(c);
            g_state[p ^ 1][dir][b * H_SZ + j0 + gq] = h;
            g_h[(b * T_SZ + trow) * DL + dir * H_SZ + j0 + gq] = h;
        }
        __threadfence();
        grid_barrier(32);
        p ^= 1;
    }
}

// ============================================================
// 3) sq/sk = h @ W1q^T, h @ W1k^T   (one warp per (b,t) row)
// ============================================================
__global__ __launch_bounds__(256) void sqsk_kernel(const float* __restrict__ W1)
{
    int wid = threadIdx.x >> 5, lane = threadIdx.x & 31;
    int r = blockIdx.x * 8 + wid;
    const float4* h4 = reinterpret_cast<const float4*>(g_h) + r * 128;
    float4 hreg[4];
    #pragma unroll
    for (int c = 0; c < 4; c++) hreg[c] = h4[c * 32 + lane];
    const float4* w14 = reinterpret_cast<const float4*>(W1);
    #pragma unroll
    for (int x = 0; x < XA; x++) {
        float aq = 0.f, ak = 0.f;
        #pragma unroll
        for (int c = 0; c < 4; c++) {
            float4 wq = w14[x * 256 + c * 32 + lane];
            float4 wk = w14[x * 256 + 128 + c * 32 + lane];
            aq = fmaf(hreg[c].x, wq.x, aq); aq = fmaf(hreg[c].y, wq.y, aq);
            aq = fmaf(hreg[c].z, wq.z, aq); aq = fmaf(hreg[c].w, wq.w, aq);
            ak = fmaf(hreg[c].x, wk.x, ak); ak = fmaf(hreg[c].y, wk.y, ak);
            ak = fmaf(hreg[c].z, wk.z, ak); ak = fmaf(hreg[c].w, wk.w, ak);
        }
        #pragma unroll
        for (int o = 16; o; o >>= 1) {
            aq += __shfl_down_sync(0xffffffffu, aq, o);
            ak += __shfl_down_sync(0xffffffffu, ak, o);
        }
        if (lane == 0) {
            g_s[r * 20 + x] = aq;
            g_s[r * 20 + 10 + x] = ak;
        }
    }
}

// ============================================================
// 4) attention scores + masked softmax (block per (b,q) row)
// ============================================================
__global__ __launch_bounds__(256) void attn_kernel(
    const float* __restrict__ mask, const float* __restrict__ W2)
{
    __shared__ float red[256];
    __shared__ float sqv[XA];
    __shared__ float w2s[XA];
    int b = blockIdx.x >> 8, q = blockIdx.x & 255;
    int tid = threadIdx.x;
    if (tid < XA) {
        sqv[tid] = g_s[(b * T_SZ + q) * 20 + tid];
        w2s[tid] = W2[tid];
    }
    __syncthreads();
    const float* skp = &g_s[(b * T_SZ + tid) * 20 + 10];
    float s = 0.f;
    #pragma unroll
    for (int x = 0; x < XA; x++) s = fmaf(w2s[x], tanhf(sqv[x] + skp[x]), s);
    if (mask[b * T_SZ + tid] == 0.0f) s = -INFINITY;
    red[tid] = s; __syncthreads();
    for (int off = 128; off; off >>= 1) {
        if (tid < off) red[tid] = fmaxf(red[tid], red[tid + off]);
        __syncthreads();
    }
    float mx = red[0]; __syncthreads();
    float e = expf(s - mx);
    red[tid] = e; __syncthreads();
    for (int off = 128; off; off >>= 1) {
        if (tid < off) red[tid] += red[tid + off];
        __syncthreads();
    }
    float inv = 1.0f / red[0];
    g_w[(b * T_SZ + q) * T_SZ + tid] = e * inv;
}

// ============================================================
// 5) context[b] = w[b] (256x256) @ h[b] (256x512)   (batched NN)
// ============================================================
__global__ __launch_bounds__(256) void gemm_ctx_kernel()
{
    __shared__ __align__(16) float As[16][68];
    __shared__ __align__(16) float Bs[16][68];
    int n0 = blockIdx.x * 64;
    int m0 = blockIdx.y * 64;
    int b = blockIdx.z;
    const float* A = g_w + b * (T_SZ * T_SZ);
    const float* Bm = g_h + b * (T_SZ * DL);
    int tid = threadIdx.x;
    int tx = tid & 15, ty = tid >> 4;
    int lr = tid >> 2, lk = (tid & 3) << 2;
    int bk = tid >> 4, bn = (tid & 15) << 2;
    float acc[4][4] = {};
    for (int k0 = 0; k0 < 256; k0 += 16) {
        float4 av = *reinterpret_cast<const float4*>(A + (m0 + lr) * 256 + k0 + lk);
        As[lk + 0][lr] = av.x; As[lk + 1][lr] = av.y; As[lk + 2][lr] = av.z; As[lk + 3][lr] = av.w;
        float4 bv = *reinterpret_cast<const float4*>(Bm + (k0 + bk) * DL + n0 + bn);
        *reinterpret_cast<float4*>(&Bs[bk][bn]) = bv;
        __syncthreads();
        #pragma unroll
        for (int k = 0; k < 16; k++) {
            float4 a4 = *reinterpret_cast<const float4*>(&As[k][ty << 2]);
            float4 b4 = *reinterpret_cast<const float4*>(&Bs[k][tx << 2]);
            float am[4] = {a4.x, a4.y, a4.z, a4.w};
            float bn4[4] = {b4.x, b4.y, b4.z, b4.w};
            #pragma unroll
            for (int i = 0; i < 4; i++)
                #pragma unroll
                for (int j = 0; j < 4; j++)
                    acc[i][j] = fmaf(am[i], bn4[j], acc[i][j]);
        }
        __syncthreads();
    }
    #pragma unroll
    for (int i = 0; i < 4; i++)
        #pragma unroll
        for (int j = 0; j < 4; j++)
            g_ctx[(b * T_SZ + m0 + (ty << 2) + i) * DL + n0 + (tx << 2) + j] = acc[i][j];
}

// ============================================================
// 6) y = [h | ctx] @ W3^T + b3   M=8192, N=512, K=1024
// ============================================================
__global__ __launch_bounds__(256) void gemm_out_kernel(
    const float* __restrict__ W3, const float* __restrict__ b3,
    float* __restrict__ out)
{
    __shared__ __align__(16) float As[16][68];
    __shared__ __align__(16) float Bs[16][68];
    int n0 = blockIdx.x * 64;
    int m0 = blockIdx.y * 64;
    int tid = threadIdx.x;
    int tx = tid & 15, ty = tid >> 4;
    int lr = tid >> 2, lk = (tid & 3) << 2;
    float acc[4][4] = {};
    for (int k0 = 0; k0 < 1024; k0 += 16) {
        int kk = k0 + lk;
        const float* Asrc = (kk < 512) ? (g_h + (m0 + lr) * DL + kk)
                                       : (g_ctx + (m0 + lr) * DL + (kk - 512));
        float4 av = *reinterpret_cast<const float4*>(Asrc);
        float4 bv = *reinterpret_cast<const float4*>(W3 + (n0 + lr) * 1024 + kk);
        As[lk + 0][lr] = av.x; As[lk + 1][lr] = av.y; As[lk + 2][lr] = av.z; As[lk + 3][lr] = av.w;
        Bs[lk + 0][lr] = bv.x; Bs[lk + 1][lr] = bv.y; Bs[lk + 2][lr] = bv.z; Bs[lk + 3][lr] = bv.w;
        __syncthreads();
        #pragma unroll
        for (int k = 0; k < 16; k++) {
            float4 a4 = *reinterpret_cast<const float4*>(&As[k][ty << 2]);
            float4 b4 = *reinterpret_cast<const float4*>(&Bs[k][tx << 2]);
            float am[4] = {a4.x, a4.y, a4.z, a4.w};
            float bn4[4] = {b4.x, b4.y, b4.z, b4.w};
            #pragma unroll
            for (int i = 0; i < 4; i++)
                #pragma unroll
                for (int j = 0; j < 4; j++)
                    acc[i][j] = fmaf(am[i], bn4[j], acc[i][j]);
        }
        __syncthreads();
    }
    #pragma unroll
    for (int i = 0; i < 4; i++) {
        int m = m0 + (ty << 2) + i;
        #pragma unroll
        for (int j = 0; j < 4; j++) {
            int n = n0 + (tx << 2) + j;
            out[m * DL + n] = acc[i][j] + b3[n];
        }
    }
}

// ============================================================
extern "C" void kernel_launch(void* const* d_in, const int* in_sizes, int n_in,
                              void* d_out, int out_size)
{
    const float* x     = (const float*)d_in[0];
    const float* mask  = (const float*)d_in[1];
    const float* Wih_f = (const float*)d_in[2];
    const float* Whh_f = (const float*)d_in[3];
    const float* b_f   = (const float*)d_in[4];
    const float* Wih_b = (const float*)d_in[5];
    const float* Whh_b = (const float*)d_in[6];
    const float* b_b   = (const float*)d_in[7];
    const float* W1    = (const float*)d_in[8];
    const float* W2    = (const float*)d_in[9];
    const float* W3    = (const float*)d_in[10];
    const float* b3    = (const float*)d_in[11];
    float* out = (float*)d_out;

    // 1) input projection for both directions
    {
        dim3 grid(2048 / 64, 8192 / 64);
        gemm_xz_kernel<<<grid, 256>>>(x, Wih_f, Wih_b, b_f, b_b);
    }

    // 2) recurrence (persistent; 97.5 KB dynamic smem)
    {
        const int lstm_smem = (64 * 260 + 32 * 260) * (int)sizeof(float);
        cudaFuncSetAttribute(lstm_kernel,
                             cudaFuncAttributeMaxDynamicSharedMemorySize,
                             lstm_smem);
        lstm_kernel<<<32, 128, lstm_smem>>>(Whh_f, Whh_b);
    }

    // 3) sq / sk
    sqsk_kernel<<<(B_SZ * T_SZ) / 8, 256>>>(W1);

    // 4) scores + softmax
    attn_kernel<<<B_SZ * T_SZ, 256>>>(mask, W2);

    // 5) context
    {
        dim3 grid(DL / 64, T_SZ / 64, B_SZ);
        gemm_ctx_kernel<<<grid, 256>>>();
    }

    // 6) output projection
    {
        dim3 grid(DL / 64, 8192 / 64);
        gemm_out_kernel<<<grid, 256>>>(W3, b3, out);
    }
}

// round 3
// speedup vs baseline: 1.4115x; 1.4115x over previous
#include <cuda_runtime.h>
#include <math.h>

#define B_SZ 32
#define T_SZ 256
#define DB   768
#define H_SZ 256
#define DL   512    // 2*H
#define XA   10

// ---------------- scratch (device globals; no allocation allowed) ----------
__device__ float g_xz[B_SZ * T_SZ * 2048];   // [b][t][fwd 1024 | bwd 1024]
__device__ float g_h[B_SZ * T_SZ * DL];      // [b][t][hf 256 | hb 256]
__device__ float g_state[2][2][B_SZ * H_SZ]; // ping-pong [p][dir][b*256+j]
__device__ float g_s[B_SZ * T_SZ * 20];      // [row][sq 10 | sk 10]
__device__ float g_w[B_SZ * T_SZ * T_SZ];    // softmax weights
__device__ float g_ctx[B_SZ * T_SZ * DL];    // context
// 8 independent barrier groups, counters padded to separate cache lines
__device__ unsigned int g_barc2[8 * 32];
__device__ unsigned int g_barg2[8 * 32];

// ---------------- generation barrier over one group of blocks --------------
__device__ __forceinline__ void group_barrier(int grp, unsigned int nblocks) {
    unsigned int* barc = &g_barc2[grp * 32];
    unsigned int* barg = &g_barg2[grp * 32];
    __syncthreads();
    if (threadIdx.x == 0) {
        __threadfence();
        unsigned int gen = atomicAdd(barg, 0u);
        unsigned int a = atomicAdd(barc, 1u);
        if (a == nblocks - 1u) {
            *barc = 0u;
            __threadfence();
            atomicAdd(barg, 1u);
        } else {
            while (atomicAdd(barg, 0u) == gen) { __nanosleep(32); }
        }
        __threadfence();
    }
    __syncthreads();
}

__device__ __forceinline__ float sigmoidf_(float x) {
    return 1.0f / (1.0f + expf(-x));
}

// ============================================================
// 1) xz = x @ [Wih_f | Wih_b]^T + bias    M=8192, N=2048, K=768
// ============================================================
__global__ __launch_bounds__(256) void gemm_xz_kernel(
    const float* __restrict__ x,
    const float* __restrict__ Wf, const float* __restrict__ Wb,
    const float* __restrict__ bf, const float* __restrict__ bb)
{
    __shared__ __align__(16) float As[16][68];
    __shared__ __align__(16) float Bs[16][68];
    int n0 = blockIdx.x * 64;
    int m0 = blockIdx.y * 64;
    const float* W;
    const float* bias;
    if (n0 < 1024) { W = Wf + n0 * DB;          bias = bf + n0; }
    else           { W = Wb + (n0 - 1024) * DB; bias = bb + (n0 - 1024); }
    const float* A = x + m0 * DB;
    int tid = threadIdx.x;
    int lr = tid >> 2;            // 0..63
    int lk = (tid & 3) << 2;      // 0,4,8,12
    int tx = tid & 15, ty = tid >> 4;
    float acc[4][4] = {};
    for (int k0 = 0; k0 < DB; k0 += 16) {
        float4 av = *reinterpret_cast<const float4*>(A + lr * DB + k0 + lk);
        float4 bv = *reinterpret_cast<const float4*>(W + lr * DB + k0 + lk);
        As[lk + 0][lr] = av.x; As[lk + 1][lr] = av.y; As[lk + 2][lr] = av.z; As[lk + 3][lr] = av.w;
        Bs[lk + 0][lr] = bv.x; Bs[lk + 1][lr] = bv.y; Bs[lk + 2][lr] = bv.z; Bs[lk + 3][lr] = bv.w;
        __syncthreads();
        #pragma unroll
        for (int k = 0; k < 16; k++) {
            float4 a4 = *reinterpret_cast<const float4*>(&As[k][ty << 2]);
            float4 b4 = *reinterpret_cast<const float4*>(&Bs[k][tx << 2]);
            float am[4] = {a4.x, a4.y, a4.z, a4.w};
            float bn[4] = {b4.x, b4.y, b4.z, b4.w};
            #pragma unroll
            for (int i = 0; i < 4; i++)
                #pragma unroll
                for (int j = 0; j < 4; j++)
                    acc[i][j] = fmaf(am[i], bn[j], acc[i][j]);
        }
        __syncthreads();
    }
    #pragma unroll
    for (int i = 0; i < 4; i++) {
        int m = m0 + (ty << 2) + i;
        #pragma unroll
        for (int j = 0; j < 4; j++) {
            int nl = (tx << 2) + j;
            g_xz[m * 2048 + n0 + nl] = acc[i][j] + bias[nl];
        }
    }
}

// ============================================================
// 2) Bi-LSTM recurrence: persistent, 128 blocks x 128 threads.
//    block = (dir, batch-group of 8, 16-unit hidden chunk).
//    Thread owns one (batch, hidden-unit) cell, all 4 gates.
//    Whh slice staged in smem once; c in registers; h through L2.
//    Sync is per (dir, batch-group): 8 groups of 16 blocks.
// ============================================================
__global__ __launch_bounds__(128) void lstm_kernel(
    const float* __restrict__ Whh_f, const float* __restrict__ Whh_b)
{
    extern __shared__ float sm[];
    float* whh_s = sm;            // 64 rows x 260 (row lg = gi*16+jl)
    float* h_s = sm + 64 * 260;   // 8 rows x 260

    int tid = threadIdx.x;
    int bid = blockIdx.x;
    int dir = bid >> 6;           // 0..1
    int rem = bid & 63;
    int bg  = rem >> 4;           // 0..3  (batch group: batches bg*8..bg*8+7)
    int jc  = rem & 15;           // 0..15 (hidden chunk: units jc*16..)
    int grp = dir * 4 + bg;       // barrier group
    int j0 = jc * 16;
    int b0 = bg * 8;
    const float* Whh = dir ? Whh_b : Whh_f;

    // stage Whh slice: row lg = gi*16+jl holds Whh[gi*H + j0 + jl][:]
    for (int i = tid; i < 64 * 256; i += 128) {
        int lg = i >> 8, k = i & 255;
        int row = (lg >> 4) * H_SZ + j0 + (lg & 15);
        whh_s[lg * 260 + k] = Whh[row * H_SZ + k];
    }

    int jl = tid >> 3;            // 0..15  hidden unit (local)
    int bq = tid & 7;             // 0..7   batch (local)
    int b  = b0 + bq;

    // zero this block's slice of state buffer 0 (one cell per thread)
    g_state[0][dir][b * H_SZ + j0 + jl] = 0.0f;
    __threadfence();
    group_barrier(grp, 16);

    float c_reg = 0.0f;
    int p = 0;

    const float4* w4 = reinterpret_cast<const float4*>(whh_s);
    const float4* h4 = reinterpret_cast<const float4*>(h_s);
    float4* h4w = reinterpret_cast<float4*>(h_s);

    for (int t = 0; t < T_SZ; t++) {
        int trow = dir ? (255 - t) : t;

        // issue xz gate loads first (no dependence on barrier-protected h)
        float acc[4];
        {
            int base = (b * T_SZ + trow) * 2048 + dir * 1024 + j0 + jl;
            #pragma unroll
            for (int gi = 0; gi < 4; gi++)
                acc[gi] = g_xz[base + gi * H_SZ];
        }

        // reload previous h for this dir / batch group (bypass L1)
        const float4* src = reinterpret_cast<const float4*>(&g_state[p][dir][b0 * H_SZ]);
        #pragma unroll
        for (int u = 0; u < 4; u++) {
            int i4 = tid + u * 128;           // 0..511
            float4 v = __ldcg(src + i4);
            int bb = i4 >> 6, k4 = i4 & 63;
            h4w[bb * 65 + k4] = v;
        }
        __syncthreads();

        #pragma unroll 4
        for (int k4 = 0; k4 < 64; k4++) {
            float4 hv = h4[bq * 65 + k4];
            #pragma unroll
            for (int gi = 0; gi < 4; gi++) {
                float4 wv = w4[(jl + 16 * gi) * 65 + k4];
                acc[gi] = fmaf(hv.x, wv.x, acc[gi]);
                acc[gi] = fmaf(hv.y, wv.y, acc[gi]);
                acc[gi] = fmaf(hv.z, wv.z, acc[gi]);
                acc[gi] = fmaf(hv.w, wv.w, acc[gi]);
            }
        }

        // gates + state update (thread owns its cell for all 4 gates)
        float ig = sigmoidf_(acc[0]);
        float fg = sigmoidf_(acc[1]);
        float gg = tanhf(acc[2]);
        float og = sigmoidf_(acc[3]);
        float c = fmaf(fg, c_reg, ig * gg);
        c_reg = c;
        float h = og * tanhf(c);
        g_state[p ^ 1][dir][b * H_SZ + j0 + jl] = h;
        g_h[(b * T_SZ + trow) * DL + dir * H_SZ + j0 + jl] = h;

        __threadfence();
        group_barrier(grp, 16);
        p ^= 1;
    }
}

// ============================================================
// 3) sq/sk = h @ W1q^T, h @ W1k^T   (one warp per (b,t) row)
// ============================================================
__global__ __launch_bounds__(256) void sqsk_kernel(const float* __restrict__ W1)
{
    int wid = threadIdx.x >> 5, lane = threadIdx.x & 31;
    int r = blockIdx.x * 8 + wid;
    const float4* h4 = reinterpret_cast<const float4*>(g_h) + r * 128;
    float4 hreg[4];
    #pragma unroll
    for (int c = 0; c < 4; c++) hreg[c] = h4[c * 32 + lane];
    const float4* w14 = reinterpret_cast<const float4*>(W1);
    #pragma unroll
    for (int x = 0; x < XA; x++) {
        float aq = 0.f, ak = 0.f;
        #pragma unroll
        for (int c = 0; c < 4; c++) {
            float4 wq = w14[x * 256 + c * 32 + lane];
            float4 wk = w14[x * 256 + 128 + c * 32 + lane];
            aq = fmaf(hreg[c].x, wq.x, aq); aq = fmaf(hreg[c].y, wq.y, aq);
            aq = fmaf(hreg[c].z, wq.z, aq); aq = fmaf(hreg[c].w, wq.w, aq);
            ak = fmaf(hreg[c].x, wk.x, ak); ak = fmaf(hreg[c].y, wk.y, ak);
            ak = fmaf(hreg[c].z, wk.z, ak); ak = fmaf(hreg[c].w, wk.w, ak);
        }
        #pragma unroll
        for (int o = 16; o; o >>= 1) {
            aq += __shfl_down_sync(0xffffffffu, aq, o);
            ak += __shfl_down_sync(0xffffffffu, ak, o);
        }
        if (lane == 0) {
            g_s[r * 20 + x] = aq;
            g_s[r * 20 + 10 + x] = ak;
        }
    }
}

// ============================================================
// 4) attention scores + masked softmax (block per (b,q) row)
// ============================================================
__global__ __launch_bounds__(256) void attn_kernel(
    const float* __restrict__ mask, const float* __restrict__ W2)
{
    __shared__ float red[256];
    __shared__ float sqv[XA];
    __shared__ float w2s[XA];
    int b = blockIdx.x >> 8, q = blockIdx.x & 255;
    int tid = threadIdx.x;
    if (tid < XA) {
        sqv[tid] = g_s[(b * T_SZ + q) * 20 + tid];
        w2s[tid] = W2[tid];
    }
    __syncthreads();
    const float* skp = &g_s[(b * T_SZ + tid) * 20 + 10];
    float s = 0.f;
    #pragma unroll
    for (int x = 0; x < XA; x++) s = fmaf(w2s[x], tanhf(sqv[x] + skp[x]), s);
    if (mask[b * T_SZ + tid] == 0.0f) s = -INFINITY;
    red[tid] = s; __syncthreads();
    for (int off = 128; off; off >>= 1) {
        if (tid < off) red[tid] = fmaxf(red[tid], red[tid + off]);
        __syncthreads();
    }
    float mx = red[0]; __syncthreads();
    float e = expf(s - mx);
    red[tid] = e; __syncthreads();
    for (int off = 128; off; off >>= 1) {
        if (tid < off) red[tid] += red[tid + off];
        __syncthreads();
    }
    float inv = 1.0f / red[0];
    g_w[(b * T_SZ + q) * T_SZ + tid] = e * inv;
}

// ============================================================
// 5) context[b] = w[b] (256x256) @ h[b] (256x512)   (batched NN)
// ============================================================
__global__ __launch_bounds__(256) void gemm_ctx_kernel()
{
    __shared__ __align__(16) float As[16][68];
    __shared__ __align__(16) float Bs[16][68];
    int n0 = blockIdx.x * 64;
    int m0 = blockIdx.y * 64;
    int b = blockIdx.z;
    const float* A = g_w + b * (T_SZ * T_SZ);
    const float* Bm = g_h + b * (T_SZ * DL);
    int tid = threadIdx.x;
    int tx = tid & 15, ty = tid >> 4;
    int lr = tid >> 2, lk = (tid & 3) << 2;
    int bk = tid >> 4, bn = (tid & 15) << 2;
    float acc[4][4] = {};
    for (int k0 = 0; k0 < 256; k0 += 16) {
        float4 av = *reinterpret_cast<const float4*>(A + (m0 + lr) * 256 + k0 + lk);
        As[lk + 0][lr] = av.x; As[lk + 1][lr] = av.y; As[lk + 2][lr] = av.z; As[lk + 3][lr] = av.w;
        float4 bv = *reinterpret_cast<const float4*>(Bm + (k0 + bk) * DL + n0 + bn);
        *reinterpret_cast<float4*>(&Bs[bk][bn]) = bv;
        __syncthreads();
        #pragma unroll
        for (int k = 0; k < 16; k++) {
            float4 a4 = *reinterpret_cast<const float4*>(&As[k][ty << 2]);
            float4 b4 = *reinterpret_cast<const float4*>(&Bs[k][tx << 2]);
            float am[4] = {a4.x, a4.y, a4.z, a4.w};
            float bn4[4] = {b4.x, b4.y, b4.z, b4.w};
            #pragma unroll
            for (int i = 0; i < 4; i++)
                #pragma unroll
                for (int j = 0; j < 4; j++)
                    acc[i][j] = fmaf(am[i], bn4[j], acc[i][j]);
        }
        __syncthreads();
    }
    #pragma unroll
    for (int i = 0; i < 4; i++)
        #pragma unroll
        for (int j = 0; j < 4; j++)
            g_ctx[(b * T_SZ + m0 + (ty << 2) + i) * DL + n0 + (tx << 2) + j] = acc[i][j];
}

// ============================================================
// 6) y = [h | ctx] @ W3^T + b3   M=8192, N=512, K=1024
// ============================================================
__global__ __launch_bounds__(256) void gemm_out_kernel(
    const float* __restrict__ W3, const float* __restrict__ b3,
    float* __restrict__ out)
{
    __shared__ __align__(16) float As[16][68];
    __shared__ __align__(16) float Bs[16][68];
    int n0 = blockIdx.x * 64;
    int m0 = blockIdx.y * 64;
    int tid = threadIdx.x;
    int tx = tid & 15, ty = tid >> 4;
    int lr = tid >> 2, lk = (tid & 3) << 2;
    float acc[4][4] = {};
    for (int k0 = 0; k0 < 1024; k0 += 16) {
        int kk = k0 + lk;
        const float* Asrc = (kk < 512) ? (g_h + (m0 + lr) * DL + kk)
                                       : (g_ctx + (m0 + lr) * DL + (kk - 512));
        float4 av = *reinterpret_cast<const float4*>(Asrc);
        float4 bv = *reinterpret_cast<const float4*>(W3 + (n0 + lr) * 1024 + kk);
        As[lk + 0][lr] = av.x; As[lk + 1][lr] = av.y; As[lk + 2][lr] = av.z; As[lk + 3][lr] = av.w;
        Bs[lk + 0][lr] = bv.x; Bs[lk + 1][lr] = bv.y; Bs[lk + 2][lr] = bv.z; Bs[lk + 3][lr] = bv.w;
        __syncthreads();
        #pragma unroll
        for (int k = 0; k < 16; k++) {
            float4 a4 = *reinterpret_cast<const float4*>(&As[k][ty << 2]);
            float4 b4 = *reinterpret_cast<const float4*>(&Bs[k][tx << 2]);
            float am[4] = {a4.x, a4.y, a4.z, a4.w};
            float bn4[4] = {b4.x, b4.y, b4.z, b4.w};
            #pragma unroll
            for (int i = 0; i < 4; i++)
                #pragma unroll
                for (int j = 0; j < 4; j++)
                    acc[i][j] = fmaf(am[i], bn4[j], acc[i][j]);
        }
        __syncthreads();
    }
    #pragma unroll
    for (int i = 0; i < 4; i++) {
        int m = m0 + (ty << 2) + i;
        #pragma unroll
        for (int j = 0; j < 4; j++) {
            int n = n0 + (tx << 2) + j;
            out[m * DL + n] = acc[i][j] + b3[n];
        }
    }
}

// ============================================================
extern "C" void kernel_launch(void* const* d_in, const int* in_sizes, int n_in,
                              void* d_out, int out_size)
{
    const float* x     = (const float*)d_in[0];
    const float* mask  = (const float*)d_in[1];
    const float* Wih_f = (const float*)d_in[2];
    const float* Whh_f = (const float*)d_in[3];
    const float* b_f   = (const float*)d_in[4];
    const float* Wih_b = (const float*)d_in[5];
    const float* Whh_b = (const float*)d_in[6];
    const float* b_b   = (const float*)d_in[7];
    const float* W1    = (const float*)d_in[8];
    const float* W2    = (const float*)d_in[9];
    const float* W3    = (const float*)d_in[10];
    const float* b3    = (const float*)d_in[11];
    float* out = (float*)d_out;

    // 1) input projection for both directions
    {
        dim3 grid(2048 / 64, 8192 / 64);
        gemm_xz_kernel<<<grid, 256>>>(x, Wih_f, Wih_b, b_f, b_b);
    }

    // 2) recurrence (persistent; ~73 KB dynamic smem, 128 blocks co-resident)
    {
        const int lstm_smem = (64 * 260 + 8 * 260) * (int)sizeof(float);
        cudaFuncSetAttribute(lstm_kernel,
                             cudaFuncAttributeMaxDynamicSharedMemorySize,
                             lstm_smem);
        lstm_kernel<<<128, 128, lstm_smem>>>(Whh_f, Whh_b);
    }

    // 3) sq / sk
    sqsk_kernel<<<(B_SZ * T_SZ) / 8, 256>>>(W1);

    // 4) scores + softmax
    attn_kernel<<<B_SZ * T_SZ, 256>>>(mask, W2);

    // 5) context
    {
        dim3 grid(DL / 64, T_SZ / 64, B_SZ);
        gemm_ctx_kernel<<<grid, 256>>>();
    }

    // 6) output projection
    {
        dim3 grid(DL / 64, 8192 / 64);
        gemm_out_kernel<<<grid, 256>>>(W3, b3, out);
    }
}

// round 7
// speedup vs baseline: 1.4472x; 1.0253x over previous
#include <cuda_runtime.h>
#include <math.h>

#define B_SZ 32
#define T_SZ 256
#define DB   768
#define H_SZ 256
#define DL   512    // 2*H
#define XA   10

// ---------------- scratch (device globals; no allocation allowed) ----------
__device__ float g_xz[B_SZ * T_SZ * 2048];   // [b][t][fwd 1024 | bwd 1024]
__device__ float g_h[B_SZ * T_SZ * DL];      // [b][t][hf 256 | hb 256]
__device__ float g_state[2][2][B_SZ * H_SZ]; // ping-pong [p][dir][b*256+j]
__device__ float g_s[B_SZ * T_SZ * 20];      // [row][sq 10 | sk 10]
__device__ float g_w[B_SZ * T_SZ * T_SZ];    // softmax weights
__device__ float g_ctx[B_SZ * T_SZ * DL];    // context
// 8 independent barrier groups, counters padded to separate cache lines
__device__ unsigned int g_barc2[8 * 32];
__device__ unsigned int g_barg2[8 * 32];

// ---------------- packed f32x2 helpers (FFMA2 path) ------------------------
__device__ __forceinline__ unsigned long long fma2(
    unsigned long long a, unsigned long long b, unsigned long long c) {
    unsigned long long d;
    asm("fma.rn.f32x2 %0, %1, %2, %3;" : "=l"(d) : "l"(a), "l"(b), "l"(c));
    return d;
}
__device__ __forceinline__ unsigned long long bcast2(float a) {
    unsigned long long d;
    unsigned int u = __float_as_uint(a);
    asm("mov.b64 %0, {%1, %2};" : "=l"(d) : "r"(u), "r"(u));
    return d;
}
__device__ __forceinline__ float2 unpack2(unsigned long long v) {
    unsigned int lo, hi;
    asm("mov.b64 {%0, %1}, %2;" : "=r"(lo), "=r"(hi) : "l"(v));
    return make_float2(__uint_as_float(lo), __uint_as_float(hi));
}
__device__ __forceinline__ unsigned long long pack2(float a, float b) {
    unsigned long long d;
    asm("mov.b64 %0, {%1, %2};" : "=l"(d)
        : "r"(__float_as_uint(a)), "r"(__float_as_uint(b)));
    return d;
}

__device__ __forceinline__ float sigmoidf_(float x) {
    return 1.0f / (1.0f + expf(-x));
}

// ============================================================
// 1) xz = x @ [Wih_f | Wih_b]^T + bias    M=8192, N=2048, K=768
// ============================================================
__global__ __launch_bounds__(256) void gemm_xz_kernel(
    const float* __restrict__ x,
    const float* __restrict__ Wf, const float* __restrict__ Wb,
    const float* __restrict__ bf, const float* __restrict__ bb)
{
    __shared__ __align__(16) float As[16][68];
    __shared__ __align__(16) float Bs[16][68];
    int n0 = blockIdx.x * 64;
    int m0 = blockIdx.y * 64;
    const float* W;
    const float* bias;
    if (n0 < 1024) { W = Wf + n0 * DB;          bias = bf + n0; }
    else           { W = Wb + (n0 - 1024) * DB; bias = bb + (n0 - 1024); }
    const float* A = x + m0 * DB;
    int tid = threadIdx.x;
    int lr = tid >> 2;            // 0..63
    int lk = (tid & 3) << 2;      // 0,4,8,12
    int tx = tid & 15, ty = tid >> 4;
    unsigned long long acc2[4][2] = {};
    for (int k0 = 0; k0 < DB; k0 += 16) {
        float4 av = *reinterpret_cast<const float4*>(A + lr * DB + k0 + lk);
        float4 bv = *reinterpret_cast<const float4*>(W + lr * DB + k0 + lk);
        As[lk + 0][lr] = av.x; As[lk + 1][lr] = av.y; As[lk + 2][lr] = av.z; As[lk + 3][lr] = av.w;
        Bs[lk + 0][lr] = bv.x; Bs[lk + 1][lr] = bv.y; Bs[lk + 2][lr] = bv.z; Bs[lk + 3][lr] = bv.w;
        __syncthreads();
        #pragma unroll
        for (int k = 0; k < 16; k++) {
            float4 a4 = *reinterpret_cast<const float4*>(&As[k][ty << 2]);
            ulonglong2 bp = *reinterpret_cast<const ulonglong2*>(&Bs[k][tx << 2]);
            float am[4] = {a4.x, a4.y, a4.z, a4.w};
            #pragma unroll
            for (int i = 0; i < 4; i++) {
                unsigned long long ab = bcast2(am[i]);
                acc2[i][0] = fma2(ab, bp.x, acc2[i][0]);
                acc2[i][1] = fma2(ab, bp.y, acc2[i][1]);
            }
        }
        __syncthreads();
    }
    #pragma unroll
    for (int i = 0; i < 4; i++) {
        int m = m0 + (ty << 2) + i;
        #pragma unroll
        for (int j = 0; j < 2; j++) {
            float2 v = unpack2(acc2[i][j]);
            int nl = (tx << 2) + j * 2;
            g_xz[m * 2048 + n0 + nl]     = v.x + bias[nl];
            g_xz[m * 2048 + n0 + nl + 1] = v.y + bias[nl + 1];
        }
    }
}

// ============================================================
// 2) Bi-LSTM recurrence: persistent, 128 blocks x 128 threads.
//    block = (dir, batch-group of 8, 16-unit hidden chunk).
//    Whh staged gate-interleaved [k][jl][gate] for packed FFMA2.
//    Sync per (dir, batch-group): 8 groups of 16 blocks, with
//    split arrive/wait and xz prefetch inside the wait window.
// ============================================================
__global__ __launch_bounds__(128) void lstm_kernel(
    const float* __restrict__ Whh_f, const float* __restrict__ Whh_b)
{
    extern __shared__ float sm[];
    float* whh_s = sm;             // 256 rows (k) x 68 (16 jl x 4 gates + pad)
    float* h_s = sm + 256 * 68;    // 8 rows (bq) x 260 (k + pad)

    int tid = threadIdx.x;
    int bid = blockIdx.x;
    int dir = bid >> 6;            // 0..1
    int rem = bid & 63;
    int bg  = rem >> 4;            // 0..3
    int jc  = rem & 15;            // 0..15
    int grp = dir * 4 + bg;
    int j0 = jc * 16;
    int b0 = bg * 8;
    const float* Whh = dir ? Whh_b : Whh_f;
    unsigned int* barc = &g_barc2[grp * 32];
    unsigned int* barg = &g_barg2[grp * 32];

    // stage Whh gate-interleaved: whh_s[k*68 + jl*4 + gi] = Whh[gi*H + j0+jl][k]
    for (int i = tid; i < 256 * 64; i += 128) {
        int k = i >> 6, q = i & 63;
        int jl2 = q >> 2, gi = q & 3;
        whh_s[k * 68 + q] = Whh[(gi * H_SZ + j0 + jl2) * H_SZ + k];
    }

    int jl = tid >> 3;             // 0..15 hidden unit (local)
    int bq = tid & 7;              // 0..7  batch (local)
    int b  = b0 + bq;

    g_state[0][dir][b * H_SZ + j0 + jl] = 0.0f;
    __syncthreads();
    // initial full barrier (arrive+wait fused)
    if (tid == 0) {
        __threadfence();
        unsigned int gen = atomicAdd(barg, 0u);
        unsigned int a = atomicAdd(barc, 1u);
        if (a == 15u) { *barc = 0u; __threadfence(); atomicAdd(barg, 1u); }
        else { while (atomicAdd(barg, 0u) == gen) { __nanosleep(32); } }
        __threadfence();
    }
    __syncthreads();

    float c_reg = 0.0f;
    int p = 0;

    const float4* h4 = reinterpret_cast<const float4*>(h_s);
    float4* h4w = reinterpret_cast<float4*>(h_s);

    // prefetch xz for t=0
    float xzp[4];
    {
        int trow = dir ? 255 : 0;
        int base = (b * T_SZ + trow) * 2048 + dir * 1024 + j0 + jl;
        #pragma unroll
        for (int gi = 0; gi < 4; gi++) xzp[gi] = g_xz[base + gi * H_SZ];
    }

    for (int t = 0; t < T_SZ; t++) {
        int trow = dir ? (255 - t) : t;

        // reload previous h for this dir / batch group (bypass L1)
        const float4* src = reinterpret_cast<const float4*>(&g_state[p][dir][b0 * H_SZ]);
        #pragma unroll
        for (int u = 0; u < 4; u++) {
            int i4 = tid + u * 128;           // 0..511
            float4 v = __ldcg(src + i4);
            int bb = i4 >> 6, k4 = i4 & 63;
            h4w[bb * 65 + k4] = v;
        }
        __syncthreads();

        // gates packed: acc01 = (i,f), acc23 = (g,o)
        unsigned long long acc01 = pack2(xzp[0], xzp[1]);
        unsigned long long acc23 = pack2(xzp[2], xzp[3]);

        #pragma unroll 4
        for (int k4 = 0; k4 < 64; k4++) {
            float4 hv = h4[bq * 65 + k4];
            float he[4] = {hv.x, hv.y, hv.z, hv.w};
            #pragma unroll
            for (int e = 0; e < 4; e++) {
                int k = k4 * 4 + e;
                unsigned long long hb = bcast2(he[e]);
                ulonglong2 wp = *reinterpret_cast<const ulonglong2*>(
                    &whh_s[k * 68 + (jl << 2)]);
                acc01 = fma2(hb, wp.x, acc01);
                acc23 = fma2(hb, wp.y, acc23);
            }
        }

        float2 v01 = unpack2(acc01);
        float2 v23 = unpack2(acc23);
        float ig = sigmoidf_(v01.x);
        float fg = sigmoidf_(v01.y);
        float gg = tanhf(v23.x);
        float og = sigmoidf_(v23.y);
        float c = fmaf(fg, c_reg, ig * gg);
        c_reg = c;
        float h = og * tanhf(c);
        g_state[p ^ 1][dir][b * H_SZ + j0 + jl] = h;
        g_h[(b * T_SZ + trow) * DL + dir * H_SZ + j0 + jl] = h;

        // ---- split barrier: arrive, prefetch next xz, then wait ----
        __syncthreads();
        unsigned int gen = 0u;
        bool last = false;
        if (tid == 0) {
            __threadfence();
            gen = atomicAdd(barg, 0u);
            unsigned int a = atomicAdd(barc, 1u);
            if (a == 15u) { *barc = 0u; __threadfence(); atomicAdd(barg, 1u); last = true; }
        }
        // prefetch xz for t+1 while others arrive
        if (t + 1 < T_SZ) {
            int tnext = dir ? (254 - t) : (t + 1);
            int base = (b * T_SZ + tnext) * 2048 + dir * 1024 + j0 + jl;
            #pragma unroll
            for (int gi = 0; gi < 4; gi++) xzp[gi] = g_xz[base + gi * H_SZ];
        }
        if (tid == 0) {
            if (!last) { while (atomicAdd(barg, 0u) == gen) { __nanosleep(32); } }
            __threadfence();
        }
        __syncthreads();
        p ^= 1;
    }
}

// ============================================================
// 3) sq/sk = h @ W1q^T, h @ W1k^T   (one warp per (b,t) row)
// ============================================================
__global__ __launch_bounds__(256) void sqsk_kernel(const float* __restrict__ W1)
{
    int wid = threadIdx.x >> 5, lane = threadIdx.x & 31;
    int r = blockIdx.x * 8 + wid;
    const float4* h4 = reinterpret_cast<const float4*>(g_h) + r * 128;
    float4 hreg[4];
    #pragma unroll
    for (int c = 0; c < 4; c++) hreg[c] = h4[c * 32 + lane];
    const float4* w14 = reinterpret_cast<const float4*>(W1);
    #pragma unroll
    for (int x = 0; x < XA; x++) {
        float aq = 0.f, ak = 0.f;
        #pragma unroll
        for (int c = 0; c < 4; c++) {
            float4 wq = w14[x * 256 + c * 32 + lane];
            float4 wk = w14[x * 256 + 128 + c * 32 + lane];
            aq = fmaf(hreg[c].x, wq.x, aq); aq = fmaf(hreg[c].y, wq.y, aq);
            aq = fmaf(hreg[c].z, wq.z, aq); aq = fmaf(hreg[c].w, wq.w, aq);
            ak = fmaf(hreg[c].x, wk.x, ak); ak = fmaf(hreg[c].y, wk.y, ak);
            ak = fmaf(hreg[c].z, wk.z, ak); ak = fmaf(hreg[c].w, wk.w, ak);
        }
        #pragma unroll
        for (int o = 16; o; o >>= 1) {
            aq += __shfl_down_sync(0xffffffffu, aq, o);
            ak += __shfl_down_sync(0xffffffffu, ak, o);
        }
        if (lane == 0) {
            g_s[r * 20 + x] = aq;
            g_s[r * 20 + 10 + x] = ak;
        }
    }
}

// ============================================================
// 4) attention scores + masked softmax (block per (b,q) row)
// ============================================================
__global__ __launch_bounds__(256) void attn_kernel(
    const float* __restrict__ mask, const float* __restrict__ W2)
{
    __shared__ float red[256];
    __shared__ float sqv[XA];
    __shared__ float w2s[XA];
    int b = blockIdx.x >> 8, q = blockIdx.x & 255;
    int tid = threadIdx.x;
    if (tid < XA) {
        sqv[tid] = g_s[(b * T_SZ + q) * 20 + tid];
        w2s[tid] = W2[tid];
    }
    __syncthreads();
    const float* skp = &g_s[(b * T_SZ + tid) * 20 + 10];
    float s = 0.f;
    #pragma unroll
    for (int x = 0; x < XA; x++) s = fmaf(w2s[x], tanhf(sqv[x] + skp[x]), s);
    if (mask[b * T_SZ + tid] == 0.0f) s = -INFINITY;
    red[tid] = s; __syncthreads();
    for (int off = 128; off; off >>= 1) {
        if (tid < off) red[tid] = fmaxf(red[tid], red[tid + off]);
        __syncthreads();
    }
    float mx = red[0]; __syncthreads();
    float e = expf(s - mx);
    red[tid] = e; __syncthreads();
    for (int off = 128; off; off >>= 1) {
        if (tid < off) red[tid] += red[tid + off];
        __syncthreads();
    }
    float inv = 1.0f / red[0];
    g_w[(b * T_SZ + q) * T_SZ + tid] = e * inv;
}

// ============================================================
// 5) context[b] = w[b] (256x256) @ h[b] (256x512)   (batched NN)
// ============================================================
__global__ __launch_bounds__(256) void gemm_ctx_kernel()
{
    __shared__ __align__(16) float As[16][68];
    __shared__ __align__(16) float Bs[16][68];
    int n0 = blockIdx.x * 64;
    int m0 = blockIdx.y * 64;
    int b = blockIdx.z;
    const float* A = g_w + b * (T_SZ * T_SZ);
    const float* Bm = g_h + b * (T_SZ * DL);
    int tid = threadIdx.x;
    int tx = tid & 15, ty = tid >> 4;
    int lr = tid >> 2, lk = (tid & 3) << 2;
    int bk = tid >> 4, bn = (tid & 15) << 2;
    unsigned long long acc2[4][2] = {};
    for (int k0 = 0; k0 < 256; k0 += 16) {
        float4 av = *reinterpret_cast<const float4*>(A + (m0 + lr) * 256 + k0 + lk);
        As[lk + 0][lr] = av.x; As[lk + 1][lr] = av.y; As[lk + 2][lr] = av.z; As[lk + 3][lr] = av.w;
        float4 bv = *reinterpret_cast<const float4*>(Bm + (k0 + bk) * DL + n0 + bn);
        *reinterpret_cast<float4*>(&Bs[bk][bn]) = bv;
        __syncthreads();
        #pragma unroll
        for (int k = 0; k < 16; k++) {
            float4 a4 = *reinterpret_cast<const float4*>(&As[k][ty << 2]);
            ulonglong2 bp = *reinterpret_cast<const ulonglong2*>(&Bs[k][tx << 2]);
            float am[4] = {a4.x, a4.y, a4.z, a4.w};
            #pragma unroll
            for (int i = 0; i < 4; i++) {
                unsigned long long ab = bcast2(am[i]);
                acc2[i][0] = fma2(ab, bp.x, acc2[i][0]);
                acc2[i][1] = fma2(ab, bp.y, acc2[i][1]);
            }
        }
        __syncthreads();
    }
    #pragma unroll
    for (int i = 0; i < 4; i++) {
        int m = m0 + (ty << 2) + i;
        #pragma unroll
        for (int j = 0; j < 2; j++) {
            float2 v = unpack2(acc2[i][j]);
            int n = n0 + (tx << 2) + j * 2;
            g_ctx[(b * T_SZ + m) * DL + n]     = v.x;
            g_ctx[(b * T_SZ + m) * DL + n + 1] = v.y;
        }
    }
}

// ============================================================
// 6) y = [h | ctx] @ W3^T + b3   M=8192, N=512, K=1024
// ============================================================
__global__ __launch_bounds__(256) void gemm_out_kernel(
    const float* __restrict__ W3, const float* __restrict__ b3,
    float* __restrict__ out)
{
    __shared__ __align__(16) float As[16][68];
    __shared__ __align__(16) float Bs[16][68];
    int n0 = blockIdx.x * 64;
    int m0 = blockIdx.y * 64;
    int tid = threadIdx.x;
    int tx = tid & 15, ty = tid >> 4;
    int lr = tid >> 2, lk = (tid & 3) << 2;
    unsigned long long acc2[4][2] = {};
    for (int k0 = 0; k0 < 1024; k0 += 16) {
        int kk = k0 + lk;
        const float* Asrc = (kk < 512) ? (g_h + (m0 + lr) * DL + kk)
                                       : (g_ctx + (m0 + lr) * DL + (kk - 512));
        float4 av = *reinterpret_cast<const float4*>(Asrc);
        float4 bv = *reinterpret_cast<const float4*>(W3 + (n0 + lr) * 1024 + kk);
        As[lk + 0][lr] = av.x; As[lk + 1][lr] = av.y; As[lk + 2][lr] = av.z; As[lk + 3][lr] = av.w;
        Bs[lk + 0][lr] = bv.x; Bs[lk + 1][lr] = bv.y; Bs[lk + 2][lr] = bv.z; Bs[lk + 3][lr] = bv.w;
        __syncthreads();
        #pragma unroll
        for (int k = 0; k < 16; k++) {
            float4 a4 = *reinterpret_cast<const float4*>(&As[k][ty << 2]);
            ulonglong2 bp = *reinterpret_cast<const ulonglong2*>(&Bs[k][tx << 2]);
            float am[4] = {a4.x, a4.y, a4.z, a4.w};
            #pragma unroll
            for (int i = 0; i < 4; i++) {
                unsigned long long ab = bcast2(am[i]);
                acc2[i][0] = fma2(ab, bp.x, acc2[i][0]);
                acc2[i][1] = fma2(ab, bp.y, acc2[i][1]);
            }
        }
        __syncthreads();
    }
    #pragma unroll
    for (int i = 0; i < 4; i++) {
        int m = m0 + (ty << 2) + i;
        #pragma unroll
        for (int j = 0; j < 2; j++) {
            float2 v = unpack2(acc2[i][j]);
            int n = n0 + (tx << 2) + j * 2;
            out[m * DL + n]     = v.x + b3[n];
            out[m * DL + n + 1] = v.y + b3[n + 1];
        }
    }
}

// ============================================================
extern "C" void kernel_launch(void* const* d_in, const int* in_sizes, int n_in,
                              void* d_out, int out_size)
{
    const float* x     = (const float*)d_in[0];
    const float* mask  = (const float*)d_in[1];
    const float* Wih_f = (const float*)d_in[2];
    const float* Whh_f = (const float*)d_in[3];
    const float* b_f   = (const float*)d_in[4];
    const float* Wih_b = (const float*)d_in[5];
    const float* Whh_b = (const float*)d_in[6];
    const float* b_b   = (const float*)d_in[7];
    const float* W1    = (const float*)d_in[8];
    const float* W2    = (const float*)d_in[9];
    const float* W3    = (const float*)d_in[10];
    const float* b3    = (const float*)d_in[11];
    float* out = (float*)d_out;

    // 1) input projection for both directions
    {
        dim3 grid(2048 / 64, 8192 / 64);
        gemm_xz_kernel<<<grid, 256>>>(x, Wih_f, Wih_b, b_f, b_b);
    }

    // 2) recurrence (persistent; ~78 KB dynamic smem, 128 blocks co-resident)
    {
        const int lstm_smem = (256 * 68 + 8 * 260) * (int)sizeof(float);
        cudaFuncSetAttribute(lstm_kernel,
                             cudaFuncAttributeMaxDynamicSharedMemorySize,
                             lstm_smem);
        lstm_kernel<<<128, 128, lstm_smem>>>(Whh_f, Whh_b);
    }

    // 3) sq / sk
    sqsk_kernel<<<(B_SZ * T_SZ) / 8, 256>>>(W1);

    // 4) scores + softmax
    attn_kernel<<<B_SZ * T_SZ, 256>>>(mask, W2);

    // 5) context
    {
        dim3 grid(DL / 64, T_SZ / 64, B_SZ);
        gemm_ctx_kernel<<<grid, 256>>>();
    }

    // 6) output projection
    {
        dim3 grid(DL / 64, 8192 / 64);
        gemm_out_kernel<<<grid, 256>>>(W3, b3, out);
    }
}

// round 11
// speedup vs baseline: 1.6326x; 1.1281x over previous
#include <cuda_runtime.h>
#include <math.h>

#define B_SZ 32
#define T_SZ 256
#define DB   768
#define H_SZ 256
#define DL   512    // 2*H
#define XA   10

// ---------------- scratch (device globals; no allocation allowed) ----------
__device__ float g_xz[B_SZ * T_SZ * 2048];   // [b][t][fwd 1024 | bwd 1024]
__device__ float g_h[B_SZ * T_SZ * DL];      // [b][t][hf 256 | hb 256]
__device__ float g_state[2][2][B_SZ * H_SZ]; // ping-pong [p][dir][b*256+j]
__device__ float g_s[B_SZ * T_SZ * 20];      // [row][sq 10 | sk 10]
__device__ float g_w[B_SZ * T_SZ * T_SZ];    // softmax weights
__device__ float g_ctx[B_SZ * T_SZ * DL];    // context
// 8 independent barrier groups, counters padded to separate cache lines
__device__ unsigned int g_barc2[8 * 32];
__device__ unsigned int g_barg2[8 * 32];

// ---------------- packed f32x2 helpers (FFMA2 path) ------------------------
__device__ __forceinline__ unsigned long long fma2(
    unsigned long long a, unsigned long long b, unsigned long long c) {
    unsigned long long d;
    asm("fma.rn.f32x2 %0, %1, %2, %3;" : "=l"(d) : "l"(a), "l"(b), "l"(c));
    return d;
}
__device__ __forceinline__ unsigned long long bcast2(float a) {
    unsigned long long d;
    unsigned int u = __float_as_uint(a);
    asm("mov.b64 %0, {%1, %2};" : "=l"(d) : "r"(u), "r"(u));
    return d;
}
__device__ __forceinline__ float2 unpack2(unsigned long long v) {
    unsigned int lo, hi;
    asm("mov.b64 {%0, %1}, %2;" : "=r"(lo), "=r"(hi) : "l"(v));
    return make_float2(__uint_as_float(lo), __uint_as_float(hi));
}
__device__ __forceinline__ unsigned long long pack2(float a, float b) {
    unsigned long long d;
    asm("mov.b64 %0, {%1, %2};" : "=l"(d)
        : "r"(__float_as_uint(a)), "r"(__float_as_uint(b)));
    return d;
}

__device__ __forceinline__ float sigmoidf_(float x) {
    return 1.0f / (1.0f + expf(-x));
}

// ============================================================
// 1) xz = x @ [Wih_f | Wih_b]^T + bias    M=8192, N=2048, K=768
//    128x64 tile, 8x4 microtile, double-buffered smem + reg prefetch
// ============================================================
__global__ __launch_bounds__(256) void gemm_xz_kernel(
    const float* __restrict__ x,
    const float* __restrict__ Wf, const float* __restrict__ Wb,
    const float* __restrict__ bf, const float* __restrict__ bb)
{
    __shared__ __align__(16) float As[2][16][132];
    __shared__ __align__(16) float Bs[2][16][68];
    int n0 = blockIdx.x * 64;
    int m0 = blockIdx.y * 128;
    const float* W;
    const float* bias;
    if (n0 < 1024) { W = Wf + n0 * DB;          bias = bf + n0; }
    else           { W = Wb + (n0 - 1024) * DB; bias = bb + (n0 - 1024); }
    const float* A = x + m0 * DB;
    int tid = threadIdx.x;
    int ra = tid >> 1, ka = (tid & 1) << 3;   // A stage: row 0..127, k 0/8
    int nb = tid >> 2, kb = (tid & 3) << 2;   // B stage: row 0..63,  k 0,4,8,12
    int tx = tid & 15, ty = tid >> 4;

    float pa[8], pb[4];
    {
        float4 a0 = *reinterpret_cast<const float4*>(A + ra * DB + ka);
        float4 a1 = *reinterpret_cast<const float4*>(A + ra * DB + ka + 4);
        pa[0]=a0.x; pa[1]=a0.y; pa[2]=a0.z; pa[3]=a0.w;
        pa[4]=a1.x; pa[5]=a1.y; pa[6]=a1.z; pa[7]=a1.w;
        float4 b0 = *reinterpret_cast<const float4*>(W + nb * DB + kb);
        pb[0]=b0.x; pb[1]=b0.y; pb[2]=b0.z; pb[3]=b0.w;
    }
    #pragma unroll
    for (int i = 0; i < 8; i++) As[0][ka + i][ra] = pa[i];
    #pragma unroll
    for (int i = 0; i < 4; i++) Bs[0][kb + i][nb] = pb[i];
    __syncthreads();

    unsigned long long acc[8][2] = {};
    const int NT = DB / 16;   // 48
    for (int t = 0; t < NT; t++) {
        int cur = t & 1;
        if (t + 1 < NT) {
            int k0 = (t + 1) * 16;
            float4 a0 = *reinterpret_cast<const float4*>(A + ra * DB + k0 + ka);
            float4 a1 = *reinterpret_cast<const float4*>(A + ra * DB + k0 + ka + 4);
            pa[0]=a0.x; pa[1]=a0.y; pa[2]=a0.z; pa[3]=a0.w;
            pa[4]=a1.x; pa[5]=a1.y; pa[6]=a1.z; pa[7]=a1.w;
            float4 b0 = *reinterpret_cast<const float4*>(W + nb * DB + k0 + kb);
            pb[0]=b0.x; pb[1]=b0.y; pb[2]=b0.z; pb[3]=b0.w;
        }
        #pragma unroll
        for (int k = 0; k < 16; k++) {
            float4 a0 = *reinterpret_cast<const float4*>(&As[cur][k][ty << 3]);
            float4 a1 = *reinterpret_cast<const float4*>(&As[cur][k][(ty << 3) + 4]);
            ulonglong2 bp = *reinterpret_cast<const ulonglong2*>(&Bs[cur][k][tx << 2]);
            float am[8] = {a0.x,a0.y,a0.z,a0.w,a1.x,a1.y,a1.z,a1.w};
            #pragma unroll
            for (int i = 0; i < 8; i++) {
                unsigned long long ab = bcast2(am[i]);
                acc[i][0] = fma2(ab, bp.x, acc[i][0]);
                acc[i][1] = fma2(ab, bp.y, acc[i][1]);
            }
        }
        if (t + 1 < NT) {
            int nxt = cur ^ 1;
            #pragma unroll
            for (int i = 0; i < 8; i++) As[nxt][ka + i][ra] = pa[i];
            #pragma unroll
            for (int i = 0; i < 4; i++) Bs[nxt][kb + i][nb] = pb[i];
        }
        __syncthreads();
    }
    int nl = tx << 2;
    float4 bv4 = *reinterpret_cast<const float4*>(bias + nl);
    #pragma unroll
    for (int i = 0; i < 8; i++) {
        int m = m0 + (ty << 3) + i;
        float2 v0 = unpack2(acc[i][0]);
        float2 v1 = unpack2(acc[i][1]);
        float4 o = make_float4(v0.x + bv4.x, v0.y + bv4.y, v1.x + bv4.z, v1.y + bv4.w);
        *reinterpret_cast<float4*>(&g_xz[m * 2048 + n0 + nl]) = o;
    }
}

// ============================================================
// 2) Bi-LSTM recurrence (unchanged from R7 passing version)
// ============================================================
__global__ __launch_bounds__(128) void lstm_kernel(
    const float* __restrict__ Whh_f, const float* __restrict__ Whh_b)
{
    extern __shared__ float sm[];
    float* whh_s = sm;             // 256 rows (k) x 68 (16 jl x 4 gates + pad)
    float* h_s = sm + 256 * 68;    // 8 rows (bq) x 260 (k + pad)

    int tid = threadIdx.x;
    int bid = blockIdx.x;
    int dir = bid >> 6;
    int rem = bid & 63;
    int bg  = rem >> 4;
    int jc  = rem & 15;
    int grp = dir * 4 + bg;
    int j0 = jc * 16;
    int b0 = bg * 8;
    const float* Whh = dir ? Whh_b : Whh_f;
    unsigned int* barc = &g_barc2[grp * 32];
    unsigned int* barg = &g_barg2[grp * 32];

    for (int i = tid; i < 256 * 64; i += 128) {
        int k = i >> 6, q = i & 63;
        int jl2 = q >> 2, gi = q & 3;
        whh_s[k * 68 + q] = Whh[(gi * H_SZ + j0 + jl2) * H_SZ + k];
    }

    int jl = tid >> 3;
    int bq = tid & 7;
    int b  = b0 + bq;

    g_state[0][dir][b * H_SZ + j0 + jl] = 0.0f;
    __syncthreads();
    if (tid == 0) {
        __threadfence();
        unsigned int gen = atomicAdd(barg, 0u);
        unsigned int a = atomicAdd(barc, 1u);
        if (a == 15u) { *barc = 0u; __threadfence(); atomicAdd(barg, 1u); }
        else { while (atomicAdd(barg, 0u) == gen) { __nanosleep(32); } }
        __threadfence();
    }
    __syncthreads();

    float c_reg = 0.0f;
    int p = 0;

    const float4* h4 = reinterpret_cast<const float4*>(h_s);
    float4* h4w = reinterpret_cast<float4*>(h_s);

    float xzp[4];
    {
        int trow = dir ? 255 : 0;
        int base = (b * T_SZ + trow) * 2048 + dir * 1024 + j0 + jl;
        #pragma unroll
        for (int gi = 0; gi < 4; gi++) xzp[gi] = g_xz[base + gi * H_SZ];
    }

    for (int t = 0; t < T_SZ; t++) {
        int trow = dir ? (255 - t) : t;

        const float4* src = reinterpret_cast<const float4*>(&g_state[p][dir][b0 * H_SZ]);
        #pragma unroll
        for (int u = 0; u < 4; u++) {
            int i4 = tid + u * 128;
            float4 v = __ldcg(src + i4);
            int bb = i4 >> 6, k4 = i4 & 63;
            h4w[bb * 65 + k4] = v;
        }
        __syncthreads();

        unsigned long long acc01 = pack2(xzp[0], xzp[1]);
        unsigned long long acc23 = pack2(xzp[2], xzp[3]);

        #pragma unroll 4
        for (int k4 = 0; k4 < 64; k4++) {
            float4 hv = h4[bq * 65 + k4];
            float he[4] = {hv.x, hv.y, hv.z, hv.w};
            #pragma unroll
            for (int e = 0; e < 4; e++) {
                int k = k4 * 4 + e;
                unsigned long long hb = bcast2(he[e]);
                ulonglong2 wp = *reinterpret_cast<const ulonglong2*>(
                    &whh_s[k * 68 + (jl << 2)]);
                acc01 = fma2(hb, wp.x, acc01);
                acc23 = fma2(hb, wp.y, acc23);
            }
        }

        float2 v01 = unpack2(acc01);
        float2 v23 = unpack2(acc23);
        float ig = sigmoidf_(v01.x);
        float fg = sigmoidf_(v01.y);
        float gg = tanhf(v23.x);
        float og = sigmoidf_(v23.y);
        float c = fmaf(fg, c_reg, ig * gg);
        c_reg = c;
        float h = og * tanhf(c);
        g_state[p ^ 1][dir][b * H_SZ + j0 + jl] = h;
        g_h[(b * T_SZ + trow) * DL + dir * H_SZ + j0 + jl] = h;

        __syncthreads();
        unsigned int gen = 0u;
        bool last = false;
        if (tid == 0) {
            __threadfence();
            gen = atomicAdd(barg, 0u);
            unsigned int a = atomicAdd(barc, 1u);
            if (a == 15u) { *barc = 0u; __threadfence(); atomicAdd(barg, 1u); last = true; }
        }
        if (t + 1 < T_SZ) {
            int tnext = dir ? (254 - t) : (t + 1);
            int base = (b * T_SZ + tnext) * 2048 + dir * 1024 + j0 + jl;
            #pragma unroll
            for (int gi = 0; gi < 4; gi++) xzp[gi] = g_xz[base + gi * H_SZ];
        }
        if (tid == 0) {
            if (!last) { while (atomicAdd(barg, 0u) == gen) { __nanosleep(32); } }
            __threadfence();
        }
        __syncthreads();
        p ^= 1;
    }
}

// ============================================================
// 3) sq/sk = h @ W1q^T, h @ W1k^T   (one warp per (b,t) row)
// ============================================================
__global__ __launch_bounds__(256) void sqsk_kernel(const float* __restrict__ W1)
{
    int wid = threadIdx.x >> 5, lane = threadIdx.x & 31;
    int r = blockIdx.x * 8 + wid;
    const float4* h4 = reinterpret_cast<const float4*>(g_h) + r * 128;
    float4 hreg[4];
    #pragma unroll
    for (int c = 0; c < 4; c++) hreg[c] = h4[c * 32 + lane];
    const float4* w14 = reinterpret_cast<const float4*>(W1);
    #pragma unroll
    for (int x = 0; x < XA; x++) {
        float aq = 0.f, ak = 0.f;
        #pragma unroll
        for (int c = 0; c < 4; c++) {
            float4 wq = w14[x * 256 + c * 32 + lane];
            float4 wk = w14[x * 256 + 128 + c * 32 + lane];
            aq = fmaf(hreg[c].x, wq.x, aq); aq = fmaf(hreg[c].y, wq.y, aq);
            aq = fmaf(hreg[c].z, wq.z, aq); aq = fmaf(hreg[c].w, wq.w, aq);
            ak = fmaf(hreg[c].x, wk.x, ak); ak = fmaf(hreg[c].y, wk.y, ak);
            ak = fmaf(hreg[c].z, wk.z, ak); ak = fmaf(hreg[c].w, wk.w, ak);
        }
        #pragma unroll
        for (int o = 16; o; o >>= 1) {
            aq += __shfl_down_sync(0xffffffffu, aq, o);
            ak += __shfl_down_sync(0xffffffffu, ak, o);
        }
        if (lane == 0) {
            g_s[r * 20 + x] = aq;
            g_s[r * 20 + 10 + x] = ak;
        }
    }
}

// ============================================================
// 4) attention scores + masked softmax (block per (b,q) row)
// ============================================================
__global__ __launch_bounds__(256) void attn_kernel(
    const float* __restrict__ mask, const float* __restrict__ W2)
{
    __shared__ float red[256];
    __shared__ float sqv[XA];
    __shared__ float w2s[XA];
    int b = blockIdx.x >> 8, q = blockIdx.x & 255;
    int tid = threadIdx.x;
    if (tid < XA) {
        sqv[tid] = g_s[(b * T_SZ + q) * 20 + tid];
        w2s[tid] = W2[tid];
    }
    __syncthreads();
    const float* skp = &g_s[(b * T_SZ + tid) * 20 + 10];
    float s = 0.f;
    #pragma unroll
    for (int x = 0; x < XA; x++) s = fmaf(w2s[x], tanhf(sqv[x] + skp[x]), s);
    if (mask[b * T_SZ + tid] == 0.0f) s = -INFINITY;
    red[tid] = s; __syncthreads();
    for (int off = 128; off; off >>= 1) {
        if (tid < off) red[tid] = fmaxf(red[tid], red[tid + off]);
        __syncthreads();
    }
    float mx = red[0]; __syncthreads();
    float e = expf(s - mx);
    red[tid] = e; __syncthreads();
    for (int off = 128; off; off >>= 1) {
        if (tid < off) red[tid] += red[tid + off];
        __syncthreads();
    }
    float inv = 1.0f / red[0];
    g_w[(b * T_SZ + q) * T_SZ + tid] = e * inv;
}

// ============================================================
// 5) context[b] = w[b] (256x256) @ h[b] (256x512)  (batched NN,
//    128x64 tile, double-buffered)
// ============================================================
__global__ __launch_bounds__(256) void gemm_ctx_kernel()
{
    __shared__ __align__(16) float As[2][16][132];
    __shared__ __align__(16) float Bs[2][16][68];
    int n0 = blockIdx.x * 64;
    int m0 = blockIdx.y * 128;
    int b = blockIdx.z;
    const float* A = g_w + b * (T_SZ * T_SZ);
    const float* Bm = g_h + b * (T_SZ * DL);
    int tid = threadIdx.x;
    int ra = tid >> 1, ka = (tid & 1) << 3;   // A stage
    int bk = tid >> 4, bn = (tid & 15) << 2;  // B stage: [k][n] natural
    int tx = tid & 15, ty = tid >> 4;

    float pa[8], pb[4];
    {
        float4 a0 = *reinterpret_cast<const float4*>(A + ra * 256 + ka);
        float4 a1 = *reinterpret_cast<const float4*>(A + ra * 256 + ka + 4);
        pa[0]=a0.x; pa[1]=a0.y; pa[2]=a0.z; pa[3]=a0.w;
        pa[4]=a1.x; pa[5]=a1.y; pa[6]=a1.z; pa[7]=a1.w;
        float4 b0 = *reinterpret_cast<const float4*>(Bm + bk * DL + n0 + bn);
        pb[0]=b0.x; pb[1]=b0.y; pb[2]=b0.z; pb[3]=b0.w;
    }
    #pragma unroll
    for (int i = 0; i < 8; i++) As[0][ka + i][ra] = pa[i];
    *reinterpret_cast<float4*>(&Bs[0][bk][bn]) = make_float4(pb[0], pb[1], pb[2], pb[3]);
    __syncthreads();

    unsigned long long acc[8][2] = {};
    const int NT = 256 / 16;   // 16
    for (int t = 0; t < NT; t++) {
        int cur = t & 1;
        if (t + 1 < NT) {
            int k0 = (t + 1) * 16;
            float4 a0 = *reinterpret_cast<const float4*>(A + ra * 256 + k0 + ka);
            float4 a1 = *reinterpret_cast<const float4*>(A + ra * 256 + k0 + ka + 4);
            pa[0]=a0.x; pa[1]=a0.y; pa[2]=a0.z; pa[3]=a0.w;
            pa[4]=a1.x; pa[5]=a1.y; pa[6]=a1.z; pa[7]=a1.w;
            float4 b0 = *reinterpret_cast<const float4*>(Bm + (k0 + bk) * DL + n0 + bn);
            pb[0]=b0.x; pb[1]=b0.y; pb[2]=b0.z; pb[3]=b0.w;
        }
        #pragma unroll
        for (int k = 0; k < 16; k++) {
            float4 a0 = *reinterpret_cast<const float4*>(&As[cur][k][ty << 3]);
            float4 a1 = *reinterpret_cast<const float4*>(&As[cur][k][(ty << 3) + 4]);
            ulonglong2 bp = *reinterpret_cast<const ulonglong2*>(&Bs[cur][k][tx << 2]);
            float am[8] = {a0.x,a0.y,a0.z,a0.w,a1.x,a1.y,a1.z,a1.w};
            #pragma unroll
            for (int i = 0; i < 8; i++) {
                unsigned long long ab = bcast2(am[i]);
                acc[i][0] = fma2(ab, bp.x, acc[i][0]);
                acc[i][1] = fma2(ab, bp.y, acc[i][1]);
            }
        }
        if (t + 1 < NT) {
            int nxt = cur ^ 1;
            #pragma unroll
            for (int i = 0; i < 8; i++) As[nxt][ka + i][ra] = pa[i];
            *reinterpret_cast<float4*>(&Bs[nxt][bk][bn]) = make_float4(pb[0], pb[1], pb[2], pb[3]);
        }
        __syncthreads();
    }
    int nl = tx << 2;
    #pragma unroll
    for (int i = 0; i < 8; i++) {
        int m = m0 + (ty << 3) + i;
        float2 v0 = unpack2(acc[i][0]);
        float2 v1 = unpack2(acc[i][1]);
        *reinterpret_cast<float4*>(&g_ctx[(b * T_SZ + m) * DL + n0 + nl]) =
            make_float4(v0.x, v0.y, v1.x, v1.y);
    }
}

// ============================================================
// 6) y = [h | ctx] @ W3^T + b3   M=8192, N=512, K=1024
//    128x64 tile, double-buffered
// ============================================================
__global__ __launch_bounds__(256) void gemm_out_kernel(
    const float* __restrict__ W3, const float* __restrict__ b3,
    float* __restrict__ out)
{
    __shared__ __align__(16) float As[2][16][132];
    __shared__ __align__(16) float Bs[2][16][68];
    int n0 = blockIdx.x * 64;
    int m0 = blockIdx.y * 128;
    int tid = threadIdx.x;
    int ra = tid >> 1, ka = (tid & 1) << 3;
    int nb = tid >> 2, kb = (tid & 3) << 2;
    int tx = tid & 15, ty = tid >> 4;

    float pa[8], pb[4];
    {
        const float* Ar = g_h + (m0 + ra) * DL + ka;   // k0=0 < 512
        float4 a0 = *reinterpret_cast<const float4*>(Ar);
        float4 a1 = *reinterpret_cast<const float4*>(Ar + 4);
        pa[0]=a0.x; pa[1]=a0.y; pa[2]=a0.z; pa[3]=a0.w;
        pa[4]=a1.x; pa[5]=a1.y; pa[6]=a1.z; pa[7]=a1.w;
        float4 b0 = *reinterpret_cast<const float4*>(W3 + (n0 + nb) * 1024 + kb);
        pb[0]=b0.x; pb[1]=b0.y; pb[2]=b0.z; pb[3]=b0.w;
    }
    #pragma unroll
    for (int i = 0; i < 8; i++) As[0][ka + i][ra] = pa[i];
    #pragma unroll
    for (int i = 0; i < 4; i++) Bs[0][kb + i][nb] = pb[i];
    __syncthreads();

    unsigned long long acc[8][2] = {};
    const int NT = 1024 / 16;   // 64
    for (int t = 0; t < NT; t++) {
        int cur = t & 1;
        if (t + 1 < NT) {
            int k0 = (t + 1) * 16;
            int kk = k0 + ka;
            const float* Ar = (kk < 512) ? (g_h + (m0 + ra) * DL + kk)
                                         : (g_ctx + (m0 + ra) * DL + (kk - 512));
            float4 a0 = *reinterpret_cast<const float4*>(Ar);
            float4 a1 = *reinterpret_cast<const float4*>(Ar + 4);
            pa[0]=a0.x; pa[1]=a0.y; pa[2]=a0.z; pa[3]=a0.w;
            pa[4]=a1.x; pa[5]=a1.y; pa[6]=a1.z; pa[7]=a1.w;
            float4 b0 = *reinterpret_cast<const float4*>(W3 + (n0 + nb) * 1024 + k0 + kb);
            pb[0]=b0.x; pb[1]=b0.y; pb[2]=b0.z; pb[3]=b0.w;
        }
        #pragma unroll
        for (int k = 0; k < 16; k++) {
            float4 a0 = *reinterpret_cast<const float4*>(&As[cur][k][ty << 3]);
            float4 a1 = *reinterpret_cast<const float4*>(&As[cur][k][(ty << 3) + 4]);
            ulonglong2 bp = *reinterpret_cast<const ulonglong2*>(&Bs[cur][k][tx << 2]);
            float am[8] = {a0.x,a0.y,a0.z,a0.w,a1.x,a1.y,a1.z,a1.w};
            #pragma unroll
            for (int i = 0; i < 8; i++) {
                unsigned long long ab = bcast2(am[i]);
                acc[i][0] = fma2(ab, bp.x, acc[i][0]);
                acc[i][1] = fma2(ab, bp.y, acc[i][1]);
            }
        }
        if (t + 1 < NT) {
            int nxt = cur ^ 1;
            #pragma unroll
            for (int i = 0; i < 8; i++) As[nxt][ka + i][ra] = pa[i];
            #pragma unroll
            for (int i = 0; i < 4; i++) Bs[nxt][kb + i][nb] = pb[i];
        }
        __syncthreads();
    }
    int nl = tx << 2;
    float4 bv4 = *reinterpret_cast<const float4*>(b3 + n0 + nl);
    #pragma unroll
    for (int i = 0; i < 8; i++) {
        int m = m0 + (ty << 3) + i;
        float2 v0 = unpack2(acc[i][0]);
        float2 v1 = unpack2(acc[i][1]);
        *reinterpret_cast<float4*>(&out[m * DL + n0 + nl]) =
            make_float4(v0.x + bv4.x, v0.y + bv4.y, v1.x + bv4.z, v1.y + bv4.w);
    }
}

// ============================================================
extern "C" void kernel_launch(void* const* d_in, const int* in_sizes, int n_in,
                              void* d_out, int out_size)
{
    const float* x     = (const float*)d_in[0];
    const float* mask  = (const float*)d_in[1];
    const float* Wih_f = (const float*)d_in[2];
    const float* Whh_f = (const float*)d_in[3];
    const float* b_f   = (const float*)d_in[4];
    const float* Wih_b = (const float*)d_in[5];
    const float* Whh_b = (const float*)d_in[6];
    const float* b_b   = (const float*)d_in[7];
    const float* W1    = (const float*)d_in[8];
    const float* W2    = (const float*)d_in[9];
    const float* W3    = (const float*)d_in[10];
    const float* b3    = (const float*)d_in[11];
    float* out = (float*)d_out;

    // 1) input projection for both directions
    {
        dim3 grid(2048 / 64, 8192 / 128);
        gemm_xz_kernel<<<grid, 256>>>(x, Wih_f, Wih_b, b_f, b_b);
    }

    // 2) recurrence (persistent; ~78 KB dynamic smem, 128 blocks co-resident)
    {
        const int lstm_smem = (256 * 68 + 8 * 260) * (int)sizeof(float);
        cudaFuncSetAttribute(lstm_kernel,
                             cudaFuncAttributeMaxDynamicSharedMemorySize,
                             lstm_smem);
        lstm_kernel<<<128, 128, lstm_smem>>>(Whh_f, Whh_b);
    }

    // 3) sq / sk
    sqsk_kernel<<<(B_SZ * T_SZ) / 8, 256>>>(W1);

    // 4) scores + softmax
    attn_kernel<<<B_SZ * T_SZ, 256>>>(mask, W2);

    // 5) context
    {
        dim3 grid(DL / 64, T_SZ / 128, B_SZ);
        gemm_ctx_kernel<<<grid, 256>>>();
    }

    // 6) output projection
    {
        dim3 grid(DL / 64, 8192 / 128);
        gemm_out_kernel<<<grid, 256>>>(W3, b3, out);
    }
}